// round 12
// baseline (speedup 1.0000x reference)
#include <cuda_runtime.h>
#include <math.h>
#include <stdint.h>

#define T 512
#define M 5
#define H 128
#define KTOP 3
#define DK 64
#define DV 64
#define DC 32
#define NELEM 6
#define GH 512
#define NCTA 8
#define HSL 16
#define NTHR 768

typedef unsigned long long u64;

__device__ float g_keys[T * NELEM * DK];
__device__ float g_vals[T * NELEM * DV];
__device__ float g_hidden[T * M * H];
__device__ u64 g_W2[M * 96 * GH];
__device__ u64 g_Wq2[M * 64 * DK];
__device__ u64 g_Wqkc2[2 * M * 64 * DC];
__device__ u64 g_Wvc2[M * 64 * H];

// ===========================================================================
// Double-float primitives (proven R4-R11)
// ===========================================================================
struct DF { float h, l; };

__device__ __forceinline__ DF qts(float a, float b) {
    float s = a + b; float e = b - (s - a); return {s, e};
}
__device__ __forceinline__ DF tsum(float a, float b) {
    float s = a + b; float bb = s - a;
    float e = (a - (s - bb)) + (b - bb);
    return {s, e};
}
__device__ __forceinline__ DF tprod(float a, float b) {
    float p = a * b; float e = fmaf(a, b, -p); return {p, e};
}
__device__ __forceinline__ DF df_add(DF a, DF b) {
    DF s = tsum(a.h, b.h);
    return qts(s.h, s.l + (a.l + b.l));
}
__device__ __forceinline__ DF df_add_f(DF a, float b) {
    DF s = tsum(a.h, b);
    return qts(s.h, s.l + a.l);
}
__device__ __forceinline__ DF df_sub(DF a, DF b) { return df_add(a, {-b.h, -b.l}); }
__device__ __forceinline__ DF df_mul(DF a, DF b) {
    DF p = tprod(a.h, b.h);
    float l = p.l + (a.h * b.l + a.l * b.h);
    return qts(p.h, l);
}
__device__ __forceinline__ DF df_recip(DF d) {
    float y0 = __frcp_rn(d.h);
    DF p = tprod(d.h, y0);
    float e = (1.0f - p.h) - p.l;
    e = fmaf(-d.l, y0, e);
    return qts(y0, y0 * e);
}
__device__ __forceinline__ bool df_lt(DF a, DF b) {
    return (a.h < b.h) || (a.h == b.h && a.l < b.l);
}
__device__ __forceinline__ bool df_gt(DF a, DF b) { return df_lt(b, a); }
__device__ __forceinline__ void cacc(float& s, float& c, float xh, float xl, float w) {
    float p = xh * w;
    float e = fmaf(xh, w, -p);
    e = fmaf(xl, w, e);
    float t = s + p;
    float bb = t - s;
    c += ((s - (t - bb)) + (p - bb)) + e;
    s = t;
}
__device__ __forceinline__ void cacc_df(float& s, float& c, DF a, DF b) {
    float p = a.h * b.h;
    float e = fmaf(a.h, b.h, -p);
    e = fmaf(a.h, b.l, e);
    e = fmaf(a.l, b.h, e);
    float t = s + p;
    float bb = t - s;
    c += ((s - (t - bb)) + (p - bb)) + e;
    s = t;
}
__device__ __forceinline__ DF df_exp(DF x) {
    if (x.h > 30.f)  { x.h = 30.f;  x.l = 0.f; }
    if (x.h < -30.f) { x.h = -30.f; x.l = 0.f; }
    const float kf = rintf(x.h * 1.4426950408889634f);
    const float th = fmaf(-kf, 0.693145751953125f, x.h);
    const float tl = fmaf(-kf, 1.4286068203094172e-6f, x.l);
    float B = 2.7557319e-6f;
    B = fmaf(B, th, 2.4801587e-5f);
    B = fmaf(B, th, 1.9841270e-4f);
    B = fmaf(B, th, 1.3888889e-3f);
    B = fmaf(B, th, 8.3333333e-3f);
    B = fmaf(B, th, 4.1666667e-2f);
    DF t2 = tprod(th, th);
    DF t3 = tprod(t2.h, th);
    t3.l = fmaf(t2.l, th, t3.l);
    DF q = tprod(t3.h, 0.16666667f);
    q.l = fmaf(t3.h, -4.9670537e-9f, q.l);
    q.l = fmaf(t3.l, 0.16666667f, q.l);
    const float f4 = t2.h * t2.h * B;
    DF S = qts(1.0f, th);
    S = df_add(S, {t2.h * 0.5f, t2.l * 0.5f});
    S = df_add(S, q);
    S.l += f4;
    S.l = fmaf(S.h, tl, S.l);
    S = qts(S.h, S.l);
    const float sc = __int_as_float(((int)kf + 127) << 23);
    S.h *= sc; S.l *= sc;
    return S;
}
__device__ __forceinline__ DF df_sigmoid(DF x) {
    DF E = df_exp({-x.h, -x.l});
    return df_recip(df_add_f(E, 1.0f));
}
__device__ __forceinline__ DF df_tanh(DF x) {
    const float sgn = (x.h < 0.f) ? -1.f : 1.f;
    DF a = {sgn * x.h, sgn * x.l};
    DF E = df_exp({2.f * a.h, 2.f * a.l});
    DF r = df_recip(df_add_f(E, 1.0f));
    DF res = tsum(1.0f, -2.f * r.h);
    DF o = qts(res.h, res.l - 2.f * r.l);
    return {sgn * o.h, sgn * o.l};
}
__device__ __forceinline__ DF df_red(DF a, unsigned off) {
    float oh = __shfl_down_sync(0xffffffffu, a.h, off);
    float ol = __shfl_down_sync(0xffffffffu, a.l, off);
    return df_add(a, {oh, ol});
}

// ===========================================================================
// Packed Kahan chain (all fma.rn.f32x2). Value = s - c.
// ===========================================================================
#define PK_ONE2  0x3F8000003F800000ull
#define PK_M1_2  0xBF800000BF800000ull
__device__ __forceinline__ u64 f2fma(u64 a, u64 b, u64 c) {
    u64 r; asm("fma.rn.f32x2 %0, %1, %2, %3;" : "=l"(r) : "l"(a), "l"(b), "l"(c)); return r;
}
__device__ __forceinline__ u64 f2neg(u64 a) { return a ^ 0x8000000080000000ull; }

__device__ __forceinline__ void cacc2k(u64& s2, u64& c2, u64 xh2, u64 xl2, u64 w2) {
    u64 p  = f2fma(xh2, w2, 0ull);
    u64 e  = f2fma(xh2, w2, f2neg(p));
    e      = f2fma(xl2, w2, e);
    u64 cm = f2fma(e, PK_M1_2, c2);
    u64 y  = f2fma(cm, PK_M1_2, p);
    u64 t  = f2fma(s2, PK_ONE2, y);
    u64 d  = f2fma(s2, PK_M1_2, t);
    c2     = f2fma(y, PK_M1_2, d);
    s2 = t;
}
__device__ __forceinline__ DF df_from2k(u64 s2, u64 c2) {
    c2 = f2neg(c2);
    float se = __uint_as_float((unsigned)s2), so = __uint_as_float((unsigned)(s2 >> 32));
    float ce = __uint_as_float((unsigned)c2), co = __uint_as_float((unsigned)(c2 >> 32));
    DF re = tsum(se, ce); re = qts(re.h, re.l);
    DF ro = tsum(so, co); ro = qts(ro.h, ro.l);
    return df_add(re, ro);
}
__device__ __forceinline__ u64 f_to_lo(float a) { return (u64)__float_as_uint(a); }

// Cluster helpers
__device__ __forceinline__ uint32_t smem_u32(const void* p) {
    uint32_t a;
    asm("{ .reg .u64 t; cvta.to.shared.u64 t, %1; cvt.u32.u64 %0, t; }" : "=r"(a) : "l"(p));
    return a;
}
__device__ __forceinline__ uint32_t my_rank() {
    uint32_t r; asm("mov.u32 %0, %%cluster_ctarank;" : "=r"(r)); return r;
}
__device__ __forceinline__ void st_cluster_b32(uint32_t saddr, uint32_t rank, uint32_t v) {
    uint32_t ra;
    asm volatile("mapa.shared::cluster.u32 %0, %1, %2;" : "=r"(ra) : "r"(saddr), "r"(rank));
    asm volatile("st.shared::cluster.b32 [%0], %1;" :: "r"(ra), "r"(v) : "memory");
}
#define CLUSTER_BAR() do { \
    asm volatile("barrier.cluster.arrive.aligned;" ::: "memory"); \
    asm volatile("barrier.cluster.wait.aligned;"   ::: "memory"); } while (0)

// ---------------------------------------------------------------------------
// Kernel 0: pack weights (unchanged)
// ---------------------------------------------------------------------------
__global__ void pack_kernel(const float* __restrict__ Wq,
                            const float* __restrict__ Wih,
                            const float* __restrict__ Whh,
                            const float* __restrict__ Wqc,
                            const float* __restrict__ Wkc,
                            const float* __restrict__ Wvc)
{
    const int stride = gridDim.x * blockDim.x;
    const int i0 = blockIdx.x * blockDim.x + threadIdx.x;
    for (int idx = i0; idx < M * 96 * GH; idx += stride) {
        const int col = idx % GH;
        const int r = idx / GH;
        const int v2 = r % 96, m = r / 96;
        const int r0 = 2 * v2, r1 = r0 + 1;
        const float e = (r0 < 64) ? Wih[(m * DV + r0) * GH + col] : Whh[(m * H + r0 - 64) * GH + col];
        const float o = (r1 < 64) ? Wih[(m * DV + r1) * GH + col] : Whh[(m * H + r1 - 64) * GH + col];
        g_W2[idx] = ((u64)__float_as_uint(o) << 32) | __float_as_uint(e);
    }
    for (int idx = i0; idx < M * 64 * DK; idx += stride) {
        const int dk = idx % DK;
        const int r = idx / DK;
        const int i2 = r % 64, m = r / 64;
        const float e = Wq[(m * H + 2 * i2) * DK + dk];
        const float o = Wq[(m * H + 2 * i2 + 1) * DK + dk];
        g_Wq2[idx] = ((u64)__float_as_uint(o) << 32) | __float_as_uint(e);
    }
    for (int idx = i0; idx < 2 * M * 64 * DC; idx += stride) {
        const int dc = idx % DC;
        const int r = idx / DC;
        const int k = r % 64;
        const int pm = (r / 64) % M;
        const int sel = r / (64 * M);
        const float* W = sel ? Wkc : Wqc;
        const float e = W[(pm * H + 2 * k) * DC + dc];
        const float o = W[(pm * H + 2 * k + 1) * DC + dc];
        g_Wqkc2[idx] = ((u64)__float_as_uint(o) << 32) | __float_as_uint(e);
    }
    for (int idx = i0; idx < M * 64 * H; idx += stride) {
        const int hv = idx % H;
        const int r = idx / H;
        const int i2 = r % 64, j = r / 64;
        const float e = Wvc[(j * H + 2 * i2) * H + hv];
        const float o = Wvc[(j * H + 2 * i2 + 1) * H + hv];
        g_Wvc2[idx] = ((u64)__float_as_uint(o) << 32) | __float_as_uint(e);
    }
}

// ---------------------------------------------------------------------------
// Kernel 1: modality projections (unchanged)
// ---------------------------------------------------------------------------
__global__ void __launch_bounds__(768) proj_kernel(
    const float* __restrict__ bert,
    const int*   __restrict__ umls_idx,
    const int*   __restrict__ pos_idx,
    const float* __restrict__ disg,
    const float* __restrict__ udisg,
    const float* __restrict__ umls_table,
    const float* __restrict__ pos_table,
    const float* __restrict__ Wk0, const float* __restrict__ Wv0,
    const float* __restrict__ Wk1, const float* __restrict__ Wv1,
    const float* __restrict__ Wk2, const float* __restrict__ Wv2,
    const float* __restrict__ Wk3, const float* __restrict__ Wv3,
    const float* __restrict__ Wk4, const float* __restrict__ Wv4)
{
    __shared__ float x[768 + 50 + 20 + 2 + 2];
    const int t = blockIdx.x;
    const int tid = threadIdx.x;

    x[tid] = bert[t * 768 + tid];
    {
        const long ui = (long)umls_idx[t];
        const int  pi = pos_idx[t];
        if (tid < 50) x[768 + tid] = umls_table[ui * 50 + tid];
        else if (tid < 70) x[818 + (tid - 50)] = pos_table[pi * 20 + (tid - 50)];
        else if (tid < 72) x[838 + (tid - 70)] = disg[t * 2 + (tid - 70)];
        else if (tid < 74) x[840 + (tid - 72)] = udisg[t * 2 + (tid - 72)];
    }
    __syncthreads();

    const float* Wks[5] = {Wk0, Wk1, Wk2, Wk3, Wk4};
    const float* Wvs[5] = {Wv0, Wv1, Wv2, Wv3, Wv4};
    const int dims[5] = {768, 50, 20, 2, 2};
    const int offs[5] = {0, 768, 818, 838, 840};

    const int o    = tid;
    const int mod  = o >> 7;
    const int half = (o >> 6) & 1;
    const int dk   = o & 63;
    float acc = 0.f;
    if (mod < 5) {
        const float* W  = half ? Wvs[mod] : Wks[mod];
        const float* xx = x + offs[mod];
        const int d = dims[mod];
        for (int i = 0; i < d; i++) acc += xx[i] * W[i * 64 + dk];
    }
    if (half == 0) g_keys[t * NELEM * DK + mod * DK + dk] = acc;
    else           g_vals[t * NELEM * DV + mod * DV + dk] = acc;
}

// ---------------------------------------------------------------------------
// Kernel 2: MI-RIM scan. 8-CTA cluster, 768 thr/CTA, 2 cluster-bars/step.
// ---------------------------------------------------------------------------
__global__ void __cluster_dims__(NCTA, 1, 1) __launch_bounds__(NTHR, 1) scan_kernel(
    const float* __restrict__ blstm)
{
    __shared__ float  skt[NELEM * DK], svt[NELEM * DV];
    __shared__ float  sq_h[M * DK], sq_l[M * DK];
    __shared__ float  sat_h[M * 8], sat_l[M * 8];
    __shared__ float  sct_h[M * 8], sct_l[M * 8];
    __shared__ __align__(16) float sinp_h[M * DV];
    __shared__ __align__(16) float sinp_l[M * DV];
    __shared__ float  sgate_h[KTOP * 64], sgate_l[KTOP * 64];
    __shared__ float  sqc_h[M * DC], sqc_l[M * DC];
    __shared__ float  skc_h[M * DC], skc_l[M * DC];
    __shared__ float  svc_h[M * HSL], svc_l[M * HSL];
    __shared__ float  sc_h[M * HSL], sc_l[M * HSL];
    __shared__ __align__(16) float h1_h[M * H];
    __shared__ __align__(16) float h1_l[M * H];
    __shared__ __align__(16) float hc_h[M * H];
    __shared__ __align__(16) float hc_l[M * H];
    __shared__ float  smask[8];
    __shared__ int    ssel[4];

    const int tid  = threadIdx.x;
    const uint32_t rank = my_rank();
    const int HB = rank * HSL;
    const uint32_t a1h = smem_u32(h1_h), a1l = smem_u32(h1_l);
    const uint32_t a2h = smem_u32(hc_h), a2l = smem_u32(hc_l);

    if (tid < M * H) { hc_h[tid] = 0.f; hc_l[tid] = 0.f; }
    if (tid < M * HSL) { sc_h[tid] = 0.f; sc_l[tid] = 0.f; }
    __syncthreads();
    CLUSTER_BAR();

    for (int t = 0; t < T; ++t) {
        // ---- int1: kv load + q computed LOCALLY (K-split-2, 640 thr) ----
        if (tid < NELEM * DK) {
            skt[tid] = g_keys[t * NELEM * DK + tid];
            svt[tid] = g_vals[t * NELEM * DV + tid];
        }
        if (tid < 640) {
            const int out  = tid >> 1;            // 0..319 = (qm,dk)
            const int part = tid & 1;
            const int qm = out >> 6, dk = out & 63;
            const u64* xh2 = (const u64*)(hc_h + qm * H);
            const u64* xl2 = (const u64*)(hc_l + qm * H);
            const u64* w2  = g_Wq2 + qm * 64 * DK + dk;
            const int k0 = part * 32;
            u64 s2 = 0, c2 = 0;
            #pragma unroll 4
            for (int kk2 = 0; kk2 < 32; kk2 += 8) {
                u64 wb[8];
                #pragma unroll
                for (int k = 0; k < 8; k++) wb[k] = w2[(k0 + kk2 + k) * DK];
                #pragma unroll
                for (int k = 0; k < 8; k++)
                    cacc2k(s2, c2, xh2[k0 + kk2 + k], xl2[k0 + kk2 + k], wb[k]);
            }
            DF r = df_from2k(s2, c2);
            DF o = df_red(r, 1);
            if (part == 0) { sq_h[out] = o.h; sq_l[out] = o.l; }
        }
        __syncthreads();

        // ---- int2: attention logits + FUSED exp (shift-free softmax) ----
        {
            const int gout = tid >> 3;
            const int part = tid & 7;
            const int out = gout < 30 ? gout : 29;
            const int am = out / NELEM, j = out - am * NELEM;
            const float* kk = skt + j * DK;
            const float* qh = sq_h + am * DK;
            const float* ql = sq_l + am * DK;
            float s = 0.f, c = 0.f;
            const int i0 = part * 8;
            #pragma unroll
            for (int i = i0; i < i0 + 8; i++) cacc(s, c, qh[i], ql[i], kk[i]);
            DF r = qts(s, c);
            r = df_red(r, 4); r = df_red(r, 2); r = df_red(r, 1);
            if (part == 0 && gout < 30) {
                DF e = df_exp({r.h * 0.125f, r.l * 0.125f});
                sat_h[am * 8 + j] = e.h; sat_l[am * 8 + j] = e.l;
            }
        }
        __syncthreads();

        // ---- int3: inp dots + per-thread normalize  ||  warp22: topk ----
        if (tid < M * DV) {
            const int em = tid >> 6, dv = tid & 63;
            float s = 0.f, c = 0.f;
            #pragma unroll
            for (int j = 0; j < NELEM; j++)
                cacc(s, c, sat_h[em * 8 + j], sat_l[em * 8 + j], svt[j * DV + dv]);
            DF sum = {sat_h[em * 8], sat_l[em * 8]};
            #pragma unroll
            for (int j = 1; j < NELEM; j++) sum = df_add(sum, {sat_h[em * 8 + j], sat_l[em * 8 + j]});
            DF inv = df_recip(sum);
            DF r = df_mul(qts(s, c), inv);
            sinp_h[tid] = r.h; sinp_l[tid] = r.l;
        } else if (tid >= 704 && tid < 736) {
            const int lane = tid - 704;
            DF mysum = {0.f, 0.f};
            if (lane < M) {
                mysum = {sat_h[lane * 8], sat_l[lane * 8]};
                #pragma unroll
                for (int j = 1; j < NELEM; j++)
                    mysum = df_add(mysum, {sat_h[lane * 8 + j], sat_l[lane * 8 + j]});
            }
            DF sums[M];
            #pragma unroll
            for (int i = 0; i < M; i++) {
                sums[i].h = __shfl_sync(0xffffffffu, mysum.h, i);
                sums[i].l = __shfl_sync(0xffffffffu, mysum.l, i);
            }
            if (lane == 0) {
                bool used[M];
                #pragma unroll
                for (int i = 0; i < M; i++) { used[i] = false; smask[i] = 0.f; }
                for (int r = 0; r < KTOP; r++) {
                    int best = -1; DF bv = {0.f, 0.f};
                    for (int i = 0; i < M; i++)
                        if (!used[i] && (best < 0 || df_gt(sums[i], bv))) { bv = sums[i]; best = i; }
                    used[best] = true; smask[best] = 1.f;
                }
                int k = 0;
                for (int i = 0; i < M; i++) if (used[i]) ssel[k++] = i;
            }
        }
        __syncthreads();

        // ---- int6: gates (3 sel modules, 192 outs, K-split-4 = 768 thr) ----
        {
            const int out = tid >> 2;            // 0..191
            const int part = tid & 3;
            const int si = out >> 6;             // sel index 0..2
            const int r = out & 63;              // (gate, hl)
            const int gate = r >> 4;
            const int hl = r & 15;
            const int m = ssel[si];
            const int col = gate * H + HB + hl;
            const u64* w2 = g_W2 + (m * 96) * GH + col;
            u64 s2 = (part == 0) ? f_to_lo(blstm[m * GH + col]) : 0ull;
            u64 c2 = 0;
            const u64* ih2 = (const u64*)(sinp_h + m * DV);
            const u64* il2 = (const u64*)(sinp_l + m * DV);
            const u64* hh2 = (const u64*)(hc_h + m * H);
            const u64* hl2 = (const u64*)(hc_l + m * H);
            const int r0 = part * 24;            // 24 pairs per part
            #pragma unroll
            for (int ch = 0; ch < 2; ch++) {
                u64 wb[12];
                #pragma unroll
                for (int k = 0; k < 12; k++) wb[k] = w2[(r0 + ch * 12 + k) * GH];
                #pragma unroll
                for (int k = 0; k < 12; k++) {
                    const int row = r0 + ch * 12 + k;
                    u64 xh, xl;
                    if (row < 32) { xh = ih2[row]; xl = il2[row]; }
                    else          { xh = hh2[row - 32]; xl = hl2[row - 32]; }
                    cacc2k(s2, c2, xh, xl, wb[k]);
                }
            }
            DF g = df_from2k(s2, c2);
            g = df_red(g, 2); g = df_red(g, 1);
            if (part == 0) {
                DF nlv = (gate == 2) ? df_tanh(g) : df_sigmoid(g);
                sgate_h[si * 64 + r] = nlv.h; sgate_l[si * 64 + r] = nlv.l;
            }
        }
        __syncthreads();

        // ---- int7: LSTM update on owned slice + broadcast h1 ----
        if (tid < M * HSL) {
            const int m = tid >> 4, hl = tid & 15;
            const bool on = smask[m] > 0.5f;
            const int hg = m * H + HB + hl;
            DF h1, c1;
            if (on) {
                int si = 0;
                #pragma unroll
                for (int k = 0; k < KTOP; k++) if (ssel[k] == m) si = k;
                const int base = si * 64 + hl;
                DF ig = {sgate_h[base],      sgate_l[base]};
                DF fg = {sgate_h[base + 16], sgate_l[base + 16]};
                DF gt = {sgate_h[base + 32], sgate_l[base + 32]};
                DF og = {sgate_h[base + 48], sgate_l[base + 48]};
                DF cold = {sc_h[tid], sc_l[tid]};
                c1 = df_add(df_mul(fg, cold), df_mul(ig, gt));
                h1 = df_mul(og, df_tanh(c1));
            } else {
                h1 = {hc_h[hg], hc_l[hg]};
                c1 = {sc_h[tid], sc_l[tid]};
            }
            sc_h[tid] = c1.h; sc_l[tid] = c1.l;
            #pragma unroll
            for (int rk = 0; rk < NCTA; rk++) {
                st_cluster_b32(a1h + hg * 4, rk, __float_as_uint(h1.h));
                st_cluster_b32(a1l + hg * 4, rk, __float_as_uint(h1.l));
            }
        }
        CLUSTER_BAR();

        // ---- int8: qc/kc LOCAL (K-split-2) then vc owned (both 640 thr) ----
        if (tid < 640) {
            const int out  = tid >> 1;           // 0..319
            const int part = tid & 1;
            const int isK = out >= 160;
            const int o2 = isK ? out - 160 : out;
            const int pm = o2 >> 5, dc = o2 & 31;
            const u64* xh2 = (const u64*)(h1_h + pm * H);
            const u64* xl2 = (const u64*)(h1_l + pm * H);
            const u64* w2  = g_Wqkc2 + ((isK * 5 + pm) * 64) * DC + dc;
            const int k0 = part * 32;
            u64 s2 = 0, c2 = 0;
            #pragma unroll 4
            for (int kk2 = 0; kk2 < 32; kk2 += 8) {
                u64 wb[8];
                #pragma unroll
                for (int k = 0; k < 8; k++) wb[k] = w2[(k0 + kk2 + k) * DC];
                #pragma unroll
                for (int k = 0; k < 8; k++)
                    cacc2k(s2, c2, xh2[k0 + kk2 + k], xl2[k0 + kk2 + k], wb[k]);
            }
            DF r = df_from2k(s2, c2);
            DF o = df_red(r, 1);
            if (part == 0) {
                if (isK) { skc_h[o2] = o.h; skc_l[o2] = o.l; }
                else     { sqc_h[o2] = o.h; sqc_l[o2] = o.l; }
            }
        }
        if (tid < 640) {
            const int out = tid >> 3;            // (j, hl), 0..79
            const int part = tid & 7;
            const int j = out >> 4, hl = out & 15;
            const u64* xh2 = (const u64*)(h1_h + j * H);
            const u64* xl2 = (const u64*)(h1_l + j * H);
            const u64* w2  = g_Wvc2 + j * 64 * H + HB + hl;
            const int k0 = part * 8;
            u64 wb[8];
            #pragma unroll
            for (int k = 0; k < 8; k++) wb[k] = w2[(k0 + k) * H];
            u64 s2 = 0, c2 = 0;
            #pragma unroll
            for (int k = 0; k < 8; k++) cacc2k(s2, c2, xh2[k0 + k], xl2[k0 + k], wb[k]);
            DF r = df_from2k(s2, c2);
            r = df_red(r, 4); r = df_red(r, 2); r = df_red(r, 1);
            if (part == 0) { svc_h[out] = r.h; svc_l[out] = r.l; }
        }
        __syncthreads();

        // ---- int9: cattn logits + FUSED exp ----
        {
            const int gout = tid >> 3;
            const int part = tid & 7;
            const int out = gout < 25 ? gout : 24;
            const int im = out / M, j = out - im * M;
            float s = 0.f, c = 0.f;
            const int i0 = part * 4;
            #pragma unroll
            for (int i = i0; i < i0 + 4; i++)
                cacc_df(s, c, {sqc_h[im * DC + i], sqc_l[im * DC + i]},
                              {skc_h[j * DC + i],  skc_l[j * DC + i]});
            DF r = qts(s, c);
            r = df_red(r, 4); r = df_red(r, 2); r = df_red(r, 1);
            if (part == 0 && gout < 25) {
                DF sc = df_mul(r, {0.17677669227123260f, 3.0254043e-9f});
                DF e = df_exp(sc);
                sct_h[im * 8 + j] = e.h; sct_l[im * 8 + j] = e.l;
            }
        }
        __syncthreads();

        // ---- int12: fused normalize + h2 + emit + broadcast carry ----
        if (tid < M * HSL) {
            const int m = tid >> 4, hl = tid & 15;
            DF sum = {sct_h[m * 8], sct_l[m * 8]};
            #pragma unroll
            for (int j = 1; j < M; j++) sum = df_add(sum, {sct_h[m * 8 + j], sct_l[m * 8 + j]});
            DF inv = df_recip(sum);
            float s = 0.f, c = 0.f;
            #pragma unroll
            for (int j = 0; j < M; j++)
                cacc_df(s, c, {sct_h[m * 8 + j], sct_l[m * 8 + j]},
                              {svc_h[j * HSL + hl], svc_l[j * HSL + hl]});
            DF dot = df_mul(qts(s, c), inv);
            const int hg = m * H + HB + hl;
            DF h1 = {h1_h[hg], h1_l[hg]};
            const bool on = smask[m] > 0.5f;
            DF h2 = on ? df_add(h1, dot) : h1;
            g_hidden[t * (M * H) + hg] = h2.h + h2.l;
            #pragma unroll
            for (int rk = 0; rk < NCTA; rk++) {
                st_cluster_b32(a2h + hg * 4, rk, __float_as_uint(h2.h));
                st_cluster_b32(a2l + hg * 4, rk, __float_as_uint(h2.l));
            }
        }
        CLUSTER_BAR();
    }
}

// ---------------------------------------------------------------------------
// Kernel 3: classifier (unchanged)
// ---------------------------------------------------------------------------
__global__ void cls_kernel(const float* __restrict__ Wcls,
                           const float* __restrict__ bcls,
                           float* __restrict__ out)
{
    const int warp = (blockIdx.x * blockDim.x + threadIdx.x) >> 5;
    const int lane = threadIdx.x & 31;
    if (warp >= T * 2) return;
    const int t = warp >> 1, c = warp & 1;
    const float* h = g_hidden + t * (M * H);
    float acc = 0.f;
    for (int i = lane; i < M * H; i += 32) acc += h[i] * Wcls[i * 2 + c];
    #pragma unroll
    for (int off = 16; off; off >>= 1) acc += __shfl_down_sync(0xffffffffu, acc, off);
    if (lane == 0) out[t * 2 + c] = acc + bcls[c];
}

// ---------------------------------------------------------------------------
extern "C" void kernel_launch(void* const* d_in, const int* in_sizes, int n_in,
                              void* d_out, int out_size)
{
    const float* bert  = (const float*)d_in[0];
    const int*   ui    = (const int*)  d_in[1];
    const int*   pi    = (const int*)  d_in[2];
    const float* disg  = (const float*)d_in[3];
    const float* udisg = (const float*)d_in[4];
    const float* utab  = (const float*)d_in[5];
    const float* ptab  = (const float*)d_in[6];
    const float* Wk0 = (const float*)d_in[7],  *Wv0 = (const float*)d_in[8];
    const float* Wk1 = (const float*)d_in[9],  *Wv1 = (const float*)d_in[10];
    const float* Wk2 = (const float*)d_in[11], *Wv2 = (const float*)d_in[12];
    const float* Wk3 = (const float*)d_in[13], *Wv3 = (const float*)d_in[14];
    const float* Wk4 = (const float*)d_in[15], *Wv4 = (const float*)d_in[16];
    const float* Wq    = (const float*)d_in[17];
    const float* Wih   = (const float*)d_in[18];
    const float* Whh   = (const float*)d_in[19];
    const float* blstm = (const float*)d_in[20];
    const float* Wqc   = (const float*)d_in[21];
    const float* Wkc   = (const float*)d_in[22];
    const float* Wvc   = (const float*)d_in[23];
    const float* Wcls  = (const float*)d_in[24];
    const float* bcls  = (const float*)d_in[25];

    pack_kernel<<<256, 256>>>(Wq, Wih, Whh, Wqc, Wkc, Wvc);
    proj_kernel<<<T, 768>>>(bert, ui, pi, disg, udisg, utab, ptab,
                            Wk0, Wv0, Wk1, Wv1, Wk2, Wv2, Wk3, Wv3, Wk4, Wv4);
    scan_kernel<<<NCTA, NTHR>>>(blstm);
    cls_kernel<<<32, 1024>>>(Wcls, bcls, (float*)d_out);
}

// round 13
// speedup vs baseline: 1.2434x; 1.2434x over previous
#include <cuda_runtime.h>
#include <math.h>
#include <stdint.h>

#define T 512
#define M 5
#define H 128
#define KTOP 3
#define DK 64
#define DV 64
#define DC 32
#define NELEM 6
#define GH 512
#define NCTA 8
#define HSL 16

typedef unsigned long long u64;

__device__ float g_keys[T * NELEM * DK];
__device__ float g_vals[T * NELEM * DV];
__device__ float g_hidden[T * M * H];
__device__ u64 g_W2[M * 96 * GH];
__device__ u64 g_Wq2[M * 64 * DK];
__device__ u64 g_Wqkc2[2 * M * 64 * DC];
__device__ u64 g_Wvc2[M * 64 * H];

// ===========================================================================
// Double-float primitives (proven R4-R12)
// ===========================================================================
struct DF { float h, l; };

__device__ __forceinline__ DF qts(float a, float b) {
    float s = a + b; float e = b - (s - a); return {s, e};
}
__device__ __forceinline__ DF tsum(float a, float b) {
    float s = a + b; float bb = s - a;
    float e = (a - (s - bb)) + (b - bb);
    return {s, e};
}
__device__ __forceinline__ DF tprod(float a, float b) {
    float p = a * b; float e = fmaf(a, b, -p); return {p, e};
}
__device__ __forceinline__ DF df_add(DF a, DF b) {
    DF s = tsum(a.h, b.h);
    return qts(s.h, s.l + (a.l + b.l));
}
__device__ __forceinline__ DF df_add_f(DF a, float b) {
    DF s = tsum(a.h, b);
    return qts(s.h, s.l + a.l);
}
__device__ __forceinline__ DF df_sub(DF a, DF b) { return df_add(a, {-b.h, -b.l}); }
__device__ __forceinline__ DF df_mul(DF a, DF b) {
    DF p = tprod(a.h, b.h);
    float l = p.l + (a.h * b.l + a.l * b.h);
    return qts(p.h, l);
}
__device__ __forceinline__ DF df_recip(DF d) {
    float y0 = __frcp_rn(d.h);
    DF p = tprod(d.h, y0);
    float e = (1.0f - p.h) - p.l;
    e = fmaf(-d.l, y0, e);
    return qts(y0, y0 * e);
}
__device__ __forceinline__ bool df_lt(DF a, DF b) {
    return (a.h < b.h) || (a.h == b.h && a.l < b.l);
}
__device__ __forceinline__ bool df_gt(DF a, DF b) { return df_lt(b, a); }
__device__ __forceinline__ void cacc(float& s, float& c, float xh, float xl, float w) {
    float p = xh * w;
    float e = fmaf(xh, w, -p);
    e = fmaf(xl, w, e);
    float t = s + p;
    float bb = t - s;
    c += ((s - (t - bb)) + (p - bb)) + e;
    s = t;
}
__device__ __forceinline__ void cacc_df(float& s, float& c, DF a, DF b) {
    float p = a.h * b.h;
    float e = fmaf(a.h, b.h, -p);
    e = fmaf(a.h, b.l, e);
    e = fmaf(a.l, b.h, e);
    float t = s + p;
    float bb = t - s;
    c += ((s - (t - bb)) + (p - bb)) + e;
    s = t;
}
__device__ __forceinline__ DF df_exp(DF x) {
    if (x.h > 30.f)  { x.h = 30.f;  x.l = 0.f; }
    if (x.h < -30.f) { x.h = -30.f; x.l = 0.f; }
    const float kf = rintf(x.h * 1.4426950408889634f);
    const float th = fmaf(-kf, 0.693145751953125f, x.h);
    const float tl = fmaf(-kf, 1.4286068203094172e-6f, x.l);
    float B = 2.7557319e-6f;
    B = fmaf(B, th, 2.4801587e-5f);
    B = fmaf(B, th, 1.9841270e-4f);
    B = fmaf(B, th, 1.3888889e-3f);
    B = fmaf(B, th, 8.3333333e-3f);
    B = fmaf(B, th, 4.1666667e-2f);
    DF t2 = tprod(th, th);
    DF t3 = tprod(t2.h, th);
    t3.l = fmaf(t2.l, th, t3.l);
    DF q = tprod(t3.h, 0.16666667f);
    q.l = fmaf(t3.h, -4.9670537e-9f, q.l);
    q.l = fmaf(t3.l, 0.16666667f, q.l);
    const float f4 = t2.h * t2.h * B;
    DF S = qts(1.0f, th);
    S = df_add(S, {t2.h * 0.5f, t2.l * 0.5f});
    S = df_add(S, q);
    S.l += f4;
    S.l = fmaf(S.h, tl, S.l);
    S = qts(S.h, S.l);
    const float sc = __int_as_float(((int)kf + 127) << 23);
    S.h *= sc; S.l *= sc;
    return S;
}
__device__ __forceinline__ DF df_sigmoid(DF x) {
    DF E = df_exp({-x.h, -x.l});
    return df_recip(df_add_f(E, 1.0f));
}
__device__ __forceinline__ DF df_tanh(DF x) {
    const float sgn = (x.h < 0.f) ? -1.f : 1.f;
    DF a = {sgn * x.h, sgn * x.l};
    DF E = df_exp({2.f * a.h, 2.f * a.l});
    DF r = df_recip(df_add_f(E, 1.0f));
    DF res = tsum(1.0f, -2.f * r.h);
    DF o = qts(res.h, res.l - 2.f * r.l);
    return {sgn * o.h, sgn * o.l};
}
__device__ __forceinline__ DF df_red(DF a, unsigned off) {
    float oh = __shfl_down_sync(0xffffffffu, a.h, off);
    float ol = __shfl_down_sync(0xffffffffu, a.l, off);
    return df_add(a, {oh, ol});
}

// ===========================================================================
// Packed Kahan chain (all fma.rn.f32x2). Value = s - c.
// ===========================================================================
#define PK_ONE2  0x3F8000003F800000ull
#define PK_M1_2  0xBF800000BF800000ull
__device__ __forceinline__ u64 f2fma(u64 a, u64 b, u64 c) {
    u64 r; asm("fma.rn.f32x2 %0, %1, %2, %3;" : "=l"(r) : "l"(a), "l"(b), "l"(c)); return r;
}
__device__ __forceinline__ u64 f2neg(u64 a) { return a ^ 0x8000000080000000ull; }

__device__ __forceinline__ void cacc2k(u64& s2, u64& c2, u64 xh2, u64 xl2, u64 w2) {
    u64 p  = f2fma(xh2, w2, 0ull);
    u64 e  = f2fma(xh2, w2, f2neg(p));
    e      = f2fma(xl2, w2, e);
    u64 cm = f2fma(e, PK_M1_2, c2);
    u64 y  = f2fma(cm, PK_M1_2, p);
    u64 t  = f2fma(s2, PK_ONE2, y);
    u64 d  = f2fma(s2, PK_M1_2, t);
    c2     = f2fma(y, PK_M1_2, d);
    s2 = t;
}
__device__ __forceinline__ DF df_from2k(u64 s2, u64 c2) {
    c2 = f2neg(c2);
    float se = __uint_as_float((unsigned)s2), so = __uint_as_float((unsigned)(s2 >> 32));
    float ce = __uint_as_float((unsigned)c2), co = __uint_as_float((unsigned)(c2 >> 32));
    DF re = tsum(se, ce); re = qts(re.h, re.l);
    DF ro = tsum(so, co); ro = qts(ro.h, ro.l);
    return df_add(re, ro);
}
__device__ __forceinline__ u64 f_to_lo(float a) { return (u64)__float_as_uint(a); }

// Cluster helpers
__device__ __forceinline__ uint32_t smem_u32(const void* p) {
    uint32_t a;
    asm("{ .reg .u64 t; cvta.to.shared.u64 t, %1; cvt.u32.u64 %0, t; }" : "=r"(a) : "l"(p));
    return a;
}
__device__ __forceinline__ uint32_t my_rank() {
    uint32_t r; asm("mov.u32 %0, %%cluster_ctarank;" : "=r"(r)); return r;
}
__device__ __forceinline__ uint32_t mapa_u32(uint32_t addr, uint32_t rank) {
    uint32_t ra;
    asm("mapa.shared::cluster.u32 %0, %1, %2;" : "=r"(ra) : "r"(addr), "r"(rank));
    return ra;
}
__device__ __forceinline__ void st_cl_raw(uint32_t raddr, uint32_t v) {
    asm volatile("st.shared::cluster.b32 [%0], %1;" :: "r"(raddr), "r"(v) : "memory");
}
#define CLUSTER_BAR() do { \
    asm volatile("barrier.cluster.arrive.aligned;" ::: "memory"); \
    asm volatile("barrier.cluster.wait.aligned;"   ::: "memory"); } while (0)

// ---------------------------------------------------------------------------
// Kernel 0: pack weights (unchanged)
// ---------------------------------------------------------------------------
__global__ void pack_kernel(const float* __restrict__ Wq,
                            const float* __restrict__ Wih,
                            const float* __restrict__ Whh,
                            const float* __restrict__ Wqc,
                            const float* __restrict__ Wkc,
                            const float* __restrict__ Wvc)
{
    const int stride = gridDim.x * blockDim.x;
    const int i0 = blockIdx.x * blockDim.x + threadIdx.x;
    for (int idx = i0; idx < M * 96 * GH; idx += stride) {
        const int col = idx % GH;
        const int r = idx / GH;
        const int v2 = r % 96, m = r / 96;
        const int r0 = 2 * v2, r1 = r0 + 1;
        const float e = (r0 < 64) ? Wih[(m * DV + r0) * GH + col] : Whh[(m * H + r0 - 64) * GH + col];
        const float o = (r1 < 64) ? Wih[(m * DV + r1) * GH + col] : Whh[(m * H + r1 - 64) * GH + col];
        g_W2[idx] = ((u64)__float_as_uint(o) << 32) | __float_as_uint(e);
    }
    for (int idx = i0; idx < M * 64 * DK; idx += stride) {
        const int dk = idx % DK;
        const int r = idx / DK;
        const int i2 = r % 64, m = r / 64;
        const float e = Wq[(m * H + 2 * i2) * DK + dk];
        const float o = Wq[(m * H + 2 * i2 + 1) * DK + dk];
        g_Wq2[idx] = ((u64)__float_as_uint(o) << 32) | __float_as_uint(e);
    }
    for (int idx = i0; idx < 2 * M * 64 * DC; idx += stride) {
        const int dc = idx % DC;
        const int r = idx / DC;
        const int k = r % 64;
        const int pm = (r / 64) % M;
        const int sel = r / (64 * M);
        const float* W = sel ? Wkc : Wqc;
        const float e = W[(pm * H + 2 * k) * DC + dc];
        const float o = W[(pm * H + 2 * k + 1) * DC + dc];
        g_Wqkc2[idx] = ((u64)__float_as_uint(o) << 32) | __float_as_uint(e);
    }
    for (int idx = i0; idx < M * 64 * H; idx += stride) {
        const int hv = idx % H;
        const int r = idx / H;
        const int i2 = r % 64, j = r / 64;
        const float e = Wvc[(j * H + 2 * i2) * H + hv];
        const float o = Wvc[(j * H + 2 * i2 + 1) * H + hv];
        g_Wvc2[idx] = ((u64)__float_as_uint(o) << 32) | __float_as_uint(e);
    }
}

// ---------------------------------------------------------------------------
// Kernel 1: modality projections (unchanged)
// ---------------------------------------------------------------------------
__global__ void __launch_bounds__(768) proj_kernel(
    const float* __restrict__ bert,
    const int*   __restrict__ umls_idx,
    const int*   __restrict__ pos_idx,
    const float* __restrict__ disg,
    const float* __restrict__ udisg,
    const float* __restrict__ umls_table,
    const float* __restrict__ pos_table,
    const float* __restrict__ Wk0, const float* __restrict__ Wv0,
    const float* __restrict__ Wk1, const float* __restrict__ Wv1,
    const float* __restrict__ Wk2, const float* __restrict__ Wv2,
    const float* __restrict__ Wk3, const float* __restrict__ Wv3,
    const float* __restrict__ Wk4, const float* __restrict__ Wv4)
{
    __shared__ float x[768 + 50 + 20 + 2 + 2];
    const int t = blockIdx.x;
    const int tid = threadIdx.x;

    x[tid] = bert[t * 768 + tid];
    {
        const long ui = (long)umls_idx[t];
        const int  pi = pos_idx[t];
        if (tid < 50) x[768 + tid] = umls_table[ui * 50 + tid];
        else if (tid < 70) x[818 + (tid - 50)] = pos_table[pi * 20 + (tid - 50)];
        else if (tid < 72) x[838 + (tid - 70)] = disg[t * 2 + (tid - 70)];
        else if (tid < 74) x[840 + (tid - 72)] = udisg[t * 2 + (tid - 72)];
    }
    __syncthreads();

    const float* Wks[5] = {Wk0, Wk1, Wk2, Wk3, Wk4};
    const float* Wvs[5] = {Wv0, Wv1, Wv2, Wv3, Wv4};
    const int dims[5] = {768, 50, 20, 2, 2};
    const int offs[5] = {0, 768, 818, 838, 840};

    const int o    = tid;
    const int mod  = o >> 7;
    const int half = (o >> 6) & 1;
    const int dk   = o & 63;
    float acc = 0.f;
    if (mod < 5) {
        const float* W  = half ? Wvs[mod] : Wks[mod];
        const float* xx = x + offs[mod];
        const int d = dims[mod];
        for (int i = 0; i < d; i++) acc += xx[i] * W[i * 64 + dk];
    }
    if (half == 0) g_keys[t * NELEM * DK + mod * DK + dk] = acc;
    else           g_vals[t * NELEM * DV + mod * DV + dk] = acc;
}

// ---------------------------------------------------------------------------
// Kernel 2: MI-RIM scan. 8-CTA cluster, 640 thr/CTA, 2 cluster-bars/step.
// R10 structure + hoisted mapa deltas + warp-split int8.
// ---------------------------------------------------------------------------
__global__ void __cluster_dims__(NCTA, 1, 1) __launch_bounds__(640, 1) scan_kernel(
    const float* __restrict__ blstm)
{
    __shared__ float  skt[NELEM * DK], svt[NELEM * DV];
    __shared__ float  sq_h[M * DK], sq_l[M * DK];
    __shared__ float  sat_h[M * 8], sat_l[M * 8];
    __shared__ float  sct_h[M * 8], sct_l[M * 8];
    __shared__ __align__(16) float sinp_h[M * DV];
    __shared__ __align__(16) float sinp_l[M * DV];
    __shared__ float  sgate_h[KTOP * 64], sgate_l[KTOP * 64];
    __shared__ float  sqc_h[M * DC], sqc_l[M * DC];
    __shared__ float  skc_h[M * DC], skc_l[M * DC];
    __shared__ float  svc_h[M * HSL], svc_l[M * HSL];
    __shared__ float  sc_h[M * HSL], sc_l[M * HSL];
    __shared__ __align__(16) float h1_h[M * H];
    __shared__ __align__(16) float h1_l[M * H];
    __shared__ __align__(16) float hc_h[M * H];
    __shared__ __align__(16) float hc_l[M * H];
    __shared__ float  smask[8];
    __shared__ int    ssel[4];

    const int tid  = threadIdx.x;
    const uint32_t rank = my_rank();
    const int HB = rank * HSL;
    const uint32_t a1h = smem_u32(h1_h), a1l = smem_u32(h1_l);
    const uint32_t a2h = smem_u32(hc_h), a2l = smem_u32(hc_l);

    // loop-invariant peer-address deltas (mapa hoisted out of the t-loop)
    uint32_t delta[NCTA];
    #pragma unroll
    for (int rk = 0; rk < NCTA; rk++) delta[rk] = mapa_u32(a1h, rk) - a1h;

    hc_h[tid] = 0.f; hc_l[tid] = 0.f;
    if (tid < M * HSL) { sc_h[tid] = 0.f; sc_l[tid] = 0.f; }
    __syncthreads();
    CLUSTER_BAR();

    for (int t = 0; t < T; ++t) {
        // ---- int1: kv load + q computed LOCALLY (K-split-2) ----
        if (tid < NELEM * DK) {
            skt[tid] = g_keys[t * NELEM * DK + tid];
            svt[tid] = g_vals[t * NELEM * DV + tid];
        }
        {
            const int out  = tid >> 1;            // 0..319 = (qm,dk)
            const int part = tid & 1;
            const int qm = out >> 6, dk = out & 63;
            const u64* xh2 = (const u64*)(hc_h + qm * H);
            const u64* xl2 = (const u64*)(hc_l + qm * H);
            const u64* w2  = g_Wq2 + qm * 64 * DK + dk;
            const int k0 = part * 32;
            u64 s2 = 0, c2 = 0;
            #pragma unroll 4
            for (int kk2 = 0; kk2 < 32; kk2 += 8) {
                u64 wb[8];
                #pragma unroll
                for (int k = 0; k < 8; k++) wb[k] = w2[(k0 + kk2 + k) * DK];
                #pragma unroll
                for (int k = 0; k < 8; k++)
                    cacc2k(s2, c2, xh2[k0 + kk2 + k], xl2[k0 + kk2 + k], wb[k]);
            }
            DF r = df_from2k(s2, c2);
            DF o = df_red(r, 1);
            if (part == 0) { sq_h[out] = o.h; sq_l[out] = o.l; }
        }
        __syncthreads();

        // ---- int2: attention logits + FUSED exp (shift-free softmax) ----
        {
            const int gout = tid >> 3;
            const int part = tid & 7;
            const int out = gout < 30 ? gout : 29;
            const int am = out / NELEM, j = out - am * NELEM;
            const float* kk = skt + j * DK;
            const float* qh = sq_h + am * DK;
            const float* ql = sq_l + am * DK;
            float s = 0.f, c = 0.f;
            const int i0 = part * 8;
            #pragma unroll
            for (int i = i0; i < i0 + 8; i++) cacc(s, c, qh[i], ql[i], kk[i]);
            DF r = qts(s, c);
            r = df_red(r, 4); r = df_red(r, 2); r = df_red(r, 1);
            if (part == 0 && gout < 30) {
                DF e = df_exp({r.h * 0.125f, r.l * 0.125f});
                sat_h[am * 8 + j] = e.h; sat_l[am * 8 + j] = e.l;
            }
        }
        __syncthreads();

        // ---- int3: inp dots + per-thread normalize  ||  warp16: topk ----
        if (tid < M * DV) {
            const int em = tid >> 6, dv = tid & 63;
            float s = 0.f, c = 0.f;
            #pragma unroll
            for (int j = 0; j < NELEM; j++)
                cacc(s, c, sat_h[em * 8 + j], sat_l[em * 8 + j], svt[j * DV + dv]);
            DF sum = {sat_h[em * 8], sat_l[em * 8]};
            #pragma unroll
            for (int j = 1; j < NELEM; j++) sum = df_add(sum, {sat_h[em * 8 + j], sat_l[em * 8 + j]});
            DF inv = df_recip(sum);
            DF r = df_mul(qts(s, c), inv);
            sinp_h[tid] = r.h; sinp_l[tid] = r.l;
        } else if (tid >= 512 && tid < 544) {
            const int lane = tid - 512;
            DF mysum = {0.f, 0.f};
            if (lane < M) {
                mysum = {sat_h[lane * 8], sat_l[lane * 8]};
                #pragma unroll
                for (int j = 1; j < NELEM; j++)
                    mysum = df_add(mysum, {sat_h[lane * 8 + j], sat_l[lane * 8 + j]});
            }
            DF sums[M];
            #pragma unroll
            for (int i = 0; i < M; i++) {
                sums[i].h = __shfl_sync(0xffffffffu, mysum.h, i);
                sums[i].l = __shfl_sync(0xffffffffu, mysum.l, i);
            }
            if (lane == 0) {
                bool used[M];
                #pragma unroll
                for (int i = 0; i < M; i++) { used[i] = false; smask[i] = 0.f; }
                for (int r = 0; r < KTOP; r++) {
                    int best = -1; DF bv = {0.f, 0.f};
                    for (int i = 0; i < M; i++)
                        if (!used[i] && (best < 0 || df_gt(sums[i], bv))) { bv = sums[i]; best = i; }
                    used[best] = true; smask[best] = 1.f;
                }
                int k = 0;
                for (int i = 0; i < M; i++) if (used[i]) ssel[k++] = i;
            }
        }
        __syncthreads();

        // ---- int6: gates (3 sel modules, 192 outs, K-split-2, chunked) ----
        if (tid < KTOP * 128) {
            const int out = tid >> 1;
            const int part = tid & 1;
            const int si = out >> 6;
            const int r = out & 63;
            const int gate = r >> 4;
            const int hl = r & 15;
            const int m = ssel[si];
            const int col = gate * H + HB + hl;
            const u64* w2 = g_W2 + (m * 96) * GH + col;
            u64 s2 = part ? 0ull : f_to_lo(blstm[m * GH + col]);
            u64 c2 = 0;
            const u64* ih2 = (const u64*)(sinp_h + m * DV);
            const u64* il2 = (const u64*)(sinp_l + m * DV);
            const u64* hh2 = (const u64*)(hc_h + m * H);
            const u64* hl2 = (const u64*)(hc_l + m * H);
            const int r0 = part * 48;
            #pragma unroll
            for (int ch = 0; ch < 3; ch++) {
                u64 wb[16];
                #pragma unroll
                for (int k = 0; k < 16; k++) wb[k] = w2[(r0 + ch * 16 + k) * GH];
                #pragma unroll
                for (int k = 0; k < 16; k++) {
                    const int row = r0 + ch * 16 + k;
                    u64 xh, xl;
                    if (row < 32) { xh = ih2[row]; xl = il2[row]; }
                    else          { xh = hh2[row - 32]; xl = hl2[row - 32]; }
                    cacc2k(s2, c2, xh, xl, wb[k]);
                }
            }
            DF g = df_from2k(s2, c2);
            g = df_red(g, 1);
            if (part == 0) {
                DF nlv = (gate == 2) ? df_tanh(g) : df_sigmoid(g);
                sgate_h[si * 64 + r] = nlv.h; sgate_l[si * 64 + r] = nlv.l;
            }
        }
        __syncthreads();

        // ---- int7: LSTM update on owned slice + broadcast h1 (hoisted mapa) ----
        if (tid < M * HSL) {
            const int m = tid >> 4, hl = tid & 15;
            const bool on = smask[m] > 0.5f;
            const int hg = m * H + HB + hl;
            DF h1, c1;
            if (on) {
                int si = 0;
                #pragma unroll
                for (int k = 0; k < KTOP; k++) if (ssel[k] == m) si = k;
                const int base = si * 64 + hl;
                DF ig = {sgate_h[base],      sgate_l[base]};
                DF fg = {sgate_h[base + 16], sgate_l[base + 16]};
                DF gt = {sgate_h[base + 32], sgate_l[base + 32]};
                DF og = {sgate_h[base + 48], sgate_l[base + 48]};
                DF cold = {sc_h[tid], sc_l[tid]};
                c1 = df_add(df_mul(fg, cold), df_mul(ig, gt));
                h1 = df_mul(og, df_tanh(c1));
            } else {
                h1 = {hc_h[hg], hc_l[hg]};
                c1 = {sc_h[tid], sc_l[tid]};
            }
            sc_h[tid] = c1.h; sc_l[tid] = c1.l;
            const uint32_t dh = a1h + hg * 4, dl = a1l + hg * 4;
            #pragma unroll
            for (int rk = 0; rk < NCTA; rk++) {
                st_cl_raw(dh + delta[rk], __float_as_uint(h1.h));
                st_cl_raw(dl + delta[rk], __float_as_uint(h1.l));
            }
        }
        CLUSTER_BAR();

        // ---- int8 WARP-SPLIT: thr 0-319 qc/kc full-dot || thr 320-639 vc ----
        if (tid < 320) {
            const int out = tid;                 // 0..319
            const int isK = out >= 160;
            const int o2 = isK ? out - 160 : out;
            const int pm = o2 >> 5, dc = o2 & 31;
            const u64* xh2 = (const u64*)(h1_h + pm * H);
            const u64* xl2 = (const u64*)(h1_l + pm * H);
            const u64* w2  = g_Wqkc2 + ((isK * 5 + pm) * 64) * DC + dc;
            u64 s2 = 0, c2 = 0;
            #pragma unroll 4
            for (int kk2 = 0; kk2 < 64; kk2 += 8) {
                u64 wb[8];
                #pragma unroll
                for (int k = 0; k < 8; k++) wb[k] = w2[(kk2 + k) * DC];
                #pragma unroll
                for (int k = 0; k < 8; k++)
                    cacc2k(s2, c2, xh2[kk2 + k], xl2[kk2 + k], wb[k]);
            }
            DF r = df_from2k(s2, c2);
            if (isK) { skc_h[o2] = r.h; skc_l[o2] = r.l; }
            else     { sqc_h[o2] = r.h; sqc_l[o2] = r.l; }
        } else {
            const int tid2 = tid - 320;          // 0..319
            const int out = tid2 >> 2;           // (j, hl), 0..79
            const int part = tid2 & 3;
            const int j = out >> 4, hl = out & 15;
            const u64* xh2 = (const u64*)(h1_h + j * H);
            const u64* xl2 = (const u64*)(h1_l + j * H);
            const u64* w2  = g_Wvc2 + j * 64 * H + HB + hl;
            const int k0 = part * 16;
            u64 s2 = 0, c2 = 0;
            #pragma unroll
            for (int kk2 = 0; kk2 < 16; kk2 += 8) {
                u64 wb[8];
                #pragma unroll
                for (int k = 0; k < 8; k++) wb[k] = w2[(k0 + kk2 + k) * H];
                #pragma unroll
                for (int k = 0; k < 8; k++)
                    cacc2k(s2, c2, xh2[k0 + kk2 + k], xl2[k0 + kk2 + k], wb[k]);
            }
            DF r = df_from2k(s2, c2);
            r = df_red(r, 2); r = df_red(r, 1);
            if (part == 0) { svc_h[out] = r.h; svc_l[out] = r.l; }
        }
        __syncthreads();

        // ---- int9: cattn logits + FUSED exp ----
        {
            const int gout = tid >> 3;
            const int part = tid & 7;
            const int out = gout < 25 ? gout : 24;
            const int im = out / M, j = out - im * M;
            float s = 0.f, c = 0.f;
            const int i0 = part * 4;
            #pragma unroll
            for (int i = i0; i < i0 + 4; i++)
                cacc_df(s, c, {sqc_h[im * DC + i], sqc_l[im * DC + i]},
                              {skc_h[j * DC + i],  skc_l[j * DC + i]});
            DF r = qts(s, c);
            r = df_red(r, 4); r = df_red(r, 2); r = df_red(r, 1);
            if (part == 0 && gout < 25) {
                DF sc = df_mul(r, {0.17677669227123260f, 3.0254043e-9f});
                DF e = df_exp(sc);
                sct_h[im * 8 + j] = e.h; sct_l[im * 8 + j] = e.l;
            }
        }
        __syncthreads();

        // ---- int12: fused normalize + h2 + emit + broadcast carry ----
        if (tid < M * HSL) {
            const int m = tid >> 4, hl = tid & 15;
            DF sum = {sct_h[m * 8], sct_l[m * 8]};
            #pragma unroll
            for (int j = 1; j < M; j++) sum = df_add(sum, {sct_h[m * 8 + j], sct_l[m * 8 + j]});
            DF inv = df_recip(sum);
            float s = 0.f, c = 0.f;
            #pragma unroll
            for (int j = 0; j < M; j++)
                cacc_df(s, c, {sct_h[m * 8 + j], sct_l[m * 8 + j]},
                              {svc_h[j * HSL + hl], svc_l[j * HSL + hl]});
            DF dot = df_mul(qts(s, c), inv);
            const int hg = m * H + HB + hl;
            DF h1 = {h1_h[hg], h1_l[hg]};
            const bool on = smask[m] > 0.5f;
            DF h2 = on ? df_add(h1, dot) : h1;
            g_hidden[t * (M * H) + hg] = h2.h + h2.l;
            const uint32_t dh = a2h + hg * 4, dl = a2l + hg * 4;
            #pragma unroll
            for (int rk = 0; rk < NCTA; rk++) {
                st_cl_raw(dh + delta[rk], __float_as_uint(h2.h));
                st_cl_raw(dl + delta[rk], __float_as_uint(h2.l));
            }
        }
        CLUSTER_BAR();
    }
}

// ---------------------------------------------------------------------------
// Kernel 3: classifier (unchanged)
// ---------------------------------------------------------------------------
__global__ void cls_kernel(const float* __restrict__ Wcls,
                           const float* __restrict__ bcls,
                           float* __restrict__ out)
{
    const int warp = (blockIdx.x * blockDim.x + threadIdx.x) >> 5;
    const int lane = threadIdx.x & 31;
    if (warp >= T * 2) return;
    const int t = warp >> 1, c = warp & 1;
    const float* h = g_hidden + t * (M * H);
    float acc = 0.f;
    for (int i = lane; i < M * H; i += 32) acc += h[i] * Wcls[i * 2 + c];
    #pragma unroll
    for (int off = 16; off; off >>= 1) acc += __shfl_down_sync(0xffffffffu, acc, off);
    if (lane == 0) out[t * 2 + c] = acc + bcls[c];
}

// ---------------------------------------------------------------------------
extern "C" void kernel_launch(void* const* d_in, const int* in_sizes, int n_in,
                              void* d_out, int out_size)
{
    const float* bert  = (const float*)d_in[0];
    const int*   ui    = (const int*)  d_in[1];
    const int*   pi    = (const int*)  d_in[2];
    const float* disg  = (const float*)d_in[3];
    const float* udisg = (const float*)d_in[4];
    const float* utab  = (const float*)d_in[5];
    const float* ptab  = (const float*)d_in[6];
    const float* Wk0 = (const float*)d_in[7],  *Wv0 = (const float*)d_in[8];
    const float* Wk1 = (const float*)d_in[9],  *Wv1 = (const float*)d_in[10];
    const float* Wk2 = (const float*)d_in[11], *Wv2 = (const float*)d_in[12];
    const float* Wk3 = (const float*)d_in[13], *Wv3 = (const float*)d_in[14];
    const float* Wk4 = (const float*)d_in[15], *Wv4 = (const float*)d_in[16];
    const float* Wq    = (const float*)d_in[17];
    const float* Wih   = (const float*)d_in[18];
    const float* Whh   = (const float*)d_in[19];
    const float* blstm = (const float*)d_in[20];
    const float* Wqc   = (const float*)d_in[21];
    const float* Wkc   = (const float*)d_in[22];
    const float* Wvc   = (const float*)d_in[23];
    const float* Wcls  = (const float*)d_in[24];
    const float* bcls  = (const float*)d_in[25];

    pack_kernel<<<256, 256>>>(Wq, Wih, Whh, Wqc, Wkc, Wvc);
    proj_kernel<<<T, 768>>>(bert, ui, pi, disg, udisg, utab, ptab,
                            Wk0, Wv0, Wk1, Wv1, Wk2, Wv2, Wk3, Wv3, Wk4, Wv4);
    scan_kernel<<<NCTA, 640>>>(blstm);
    cls_kernel<<<32, 1024>>>(Wcls, bcls, (float*)d_out);
}